// round 11
// baseline (speedup 1.0000x reference)
#include <cuda_runtime.h>
#include <cstdint>

// trans_b: [32, 64, 256, 256] fp32 -> 2048 planes of 16384 float4
#define NPLANES   2048
#define PLANE_F4  16384
#define TOTAL_F4  33554432            // 2048 * 16384
#define NBATCH    32

__device__ float    g_pooled[NPLANES];   // per-plane means
__device__ float    g_scale[NPLANES];
__device__ unsigned g_bdone[NBATCH];     // planes pooled per batch (self-resetting)

// ---------------------------------------------------------------------------
// Kernel 1: per-plane global average pool + inline per-batch MLP tail.
// One block per (b,c) plane (2048 blocks). The block that finishes a batch's
// 64th plane computes that batch's SE MLP (64->4 relu ->64 sigmoid) inline,
// removing the separate MLP launch. g_bdone self-resets (atomicSub) -> safe
// across graph replays with no reset pass. 32 counters x 64 arrivals: no
// meaningful atomic contention.
// ---------------------------------------------------------------------------
__global__ void __launch_bounds__(256) se_pool_mlp_kernel(
    const float* __restrict__ x,
    const float* __restrict__ w_down,  // [4, 64]
    const float* __restrict__ b_down,  // [4]
    const float* __restrict__ w_up,    // [64, 4]
    const float* __restrict__ b_up)    // [64]
{
    const int plane = blockIdx.x;
    const float4* __restrict__ p =
        reinterpret_cast<const float4*>(x) + (size_t)plane * PLANE_F4;

    float sum = 0.0f;
    for (int i = threadIdx.x; i < PLANE_F4; i += 256) {
        float4 v = p[i];
        sum += (v.x + v.y) + (v.z + v.w);
    }

    #pragma unroll
    for (int o = 16; o > 0; o >>= 1)
        sum += __shfl_xor_sync(0xFFFFFFFFu, sum, o);

    __shared__ float sred[8];
    __shared__ int   s_last;
    const int lane = threadIdx.x & 31;
    const int w    = threadIdx.x >> 5;
    if (lane == 0) sred[w] = sum;
    __syncthreads();

    if (threadIdx.x == 0) {
        float t = (sred[0] + sred[1]) + (sred[2] + sred[3])
                + (sred[4] + sred[5]) + (sred[6] + sred[7]);
        __stcg(&g_pooled[plane], t * (1.0f / 65536.0f));
        __threadfence();                              // publish mean first
        unsigned old = atomicAdd(&g_bdone[plane >> 6], 1u);
        if (old == 63u) {
            atomicSub(&g_bdone[plane >> 6], 64u);     // self-reset for replay
            s_last = 1;
        } else {
            s_last = 0;
        }
    }
    __syncthreads();

    if (s_last) {
        // This block completed batch b: compute its MLP inline.
        const int b = plane >> 6;
        __shared__ float pooled[64];
        __shared__ float hidden[4];

        if (threadIdx.x == 0) __threadfence();        // acquire all means
        __syncthreads();

        if (threadIdx.x < 64)
            pooled[threadIdx.x] = __ldcg(&g_pooled[b * 64 + threadIdx.x]);
        __syncthreads();

        if (threadIdx.x < 4) {
            float h = b_down[threadIdx.x];
            #pragma unroll 8
            for (int k = 0; k < 64; k++)
                h = fmaf(pooled[k], __ldg(&w_down[threadIdx.x * 64 + k]), h);
            hidden[threadIdx.x] = fmaxf(h, 0.0f);
        }
        __syncthreads();

        if (threadIdx.x < 64) {
            float s = b_up[threadIdx.x];
            #pragma unroll
            for (int m = 0; m < 4; m++)
                s = fmaf(hidden[m], __ldg(&w_up[threadIdx.x * 4 + m]), s);
            g_scale[b * 64 + threadIdx.x] = 1.0f / (1.0f + expf(-s));
        }
    }
}

// ---------------------------------------------------------------------------
// Kernel 2: elementwise channel rescale, FOUR float4 per thread (ILP-4).
// Front-batched loads -> max MLP across the mixed read+write stream; then
// 4 streaming stores. Block covers 1024 consecutive float4 (one plane-aligned
// 16 KB span -> single uniform scale lookup). Reverse block order harvests
// the pool kernel's L2 tail. .cs on both sides: zero reuse.
// ---------------------------------------------------------------------------
__global__ void __launch_bounds__(256) se_scale_kernel(
    const float* __restrict__ x, float* __restrict__ y)
{
    const size_t chunk = (size_t)(gridDim.x - 1u - blockIdx.x);
    const size_t base  = chunk * 1024 + threadIdx.x;
    const float4* __restrict__ px = reinterpret_cast<const float4*>(x);
    float4*       __restrict__ py = reinterpret_cast<float4*>(y);

    const float s = g_scale[base >> 14];

    float4 v0 = __ldcs(px + base);
    float4 v1 = __ldcs(px + base + 256);
    float4 v2 = __ldcs(px + base + 512);
    float4 v3 = __ldcs(px + base + 768);

    v0.x *= s; v0.y *= s; v0.z *= s; v0.w *= s;
    v1.x *= s; v1.y *= s; v1.z *= s; v1.w *= s;
    v2.x *= s; v2.y *= s; v2.z *= s; v2.w *= s;
    v3.x *= s; v3.y *= s; v3.z *= s; v3.w *= s;

    __stcs(py + base,       v0);
    __stcs(py + base + 256, v1);
    __stcs(py + base + 512, v2);
    __stcs(py + base + 768, v3);
}

// ---------------------------------------------------------------------------
extern "C" void kernel_launch(void* const* d_in, const int* in_sizes, int n_in,
                              void* d_out, int out_size)
{
    const float* trans_b = (const float*)d_in[0];
    const float* w_down  = (const float*)d_in[1];
    const float* b_down  = (const float*)d_in[2];
    const float* w_up    = (const float*)d_in[3];
    const float* b_up    = (const float*)d_in[4];
    float* out = (float*)d_out;

    se_pool_mlp_kernel<<<NPLANES, 256>>>(trans_b, w_down, b_down, w_up, b_up);
    se_scale_kernel<<<TOTAL_F4 / 1024, 256>>>(trans_b, out);
}

// round 12
// speedup vs baseline: 1.0179x; 1.0179x over previous
#include <cuda_runtime.h>
#include <cstdint>

// trans_b: [32, 64, 256, 256] fp32 -> 2048 planes of 16384 float4
#define NPLANES    2048
#define PLANE_F4   16384
#define TOTAL_F4   33554432           // 2048 * 16384
#define NBATCH     32
#define SCALE_BLKS 32768              // TOTAL_F4 / 1024
#define SCALE_PB   1024               // scale blocks per batch

__device__ float             g_pooled[NPLANES];
__device__ float             g_scale[NPLANES];
__device__ unsigned          g_bdone[NBATCH];   // pool planes done (self-resets)
__device__ volatile unsigned g_ready[NBATCH];   // scale published (reset by last scaler)
__device__ unsigned          g_sdone[NBATCH];   // scale blocks done (self-resets)

// ---------------------------------------------------------------------------
// Single launch: blocks [0,2048) pool one plane each (+ inline MLP when a
// batch completes); blocks [2048, 2048+32768) rescale one 16 KB chunk each,
// after a one-shot read-only spin on their batch's ready flag.
//
// Deadlock-free: block dispatch follows bid order, so ALL pool blocks are
// scheduled before any scale block can hold an SM slot -> pooling always
// progresses -> every ready flag flips. Replay-safe: g_bdone/g_sdone
// self-reset via atomicSub; g_ready[b] is reset by the 1024th (last) scale
// block of batch b, which can only run after every waiter has passed.
// ---------------------------------------------------------------------------
__global__ void __launch_bounds__(256) se_onelaunch_kernel(
    const float* __restrict__ x, float* __restrict__ y,
    const float* __restrict__ w_down,  // [4, 64]
    const float* __restrict__ b_down,  // [4]
    const float* __restrict__ w_up,    // [64, 4]
    const float* __restrict__ b_up)    // [64]
{
    const int tid = threadIdx.x;

    if (blockIdx.x < NPLANES) {
        // ================= POOL (one plane) + MLP tail =====================
        const int plane = blockIdx.x;
        const float4* __restrict__ p =
            reinterpret_cast<const float4*>(x) + (size_t)plane * PLANE_F4;

        float sum = 0.0f;
        for (int i = tid; i < PLANE_F4; i += 256) {
            float4 v = p[i];                    // default policy: fill L2
            sum += (v.x + v.y) + (v.z + v.w);
        }
        #pragma unroll
        for (int o = 16; o > 0; o >>= 1)
            sum += __shfl_xor_sync(0xFFFFFFFFu, sum, o);

        __shared__ float sred[8];
        __shared__ int   s_last;
        if ((tid & 31) == 0) sred[tid >> 5] = sum;
        __syncthreads();

        if (tid == 0) {
            float t = (sred[0] + sred[1]) + (sred[2] + sred[3])
                    + (sred[4] + sred[5]) + (sred[6] + sred[7]);
            __stcg(&g_pooled[plane], t * (1.0f / 65536.0f));
            __threadfence();                    // publish mean before counting
            unsigned old = atomicAdd(&g_bdone[plane >> 6], 1u);
            if (old == 63u) {
                atomicSub(&g_bdone[plane >> 6], 64u);   // self-reset for replay
                s_last = 1;
            } else s_last = 0;
        }
        __syncthreads();

        if (s_last) {
            const int b = plane >> 6;
            __shared__ float pooled[64];
            __shared__ float hidden[4];

            if (tid == 0) __threadfence();      // acquire all 64 means
            __syncthreads();
            if (tid < 64)
                pooled[tid] = __ldcg(&g_pooled[b * 64 + tid]);
            __syncthreads();
            if (tid < 4) {
                float h = b_down[tid];
                #pragma unroll 8
                for (int k = 0; k < 64; k++)
                    h = fmaf(pooled[k], __ldg(&w_down[tid * 64 + k]), h);
                hidden[tid] = fmaxf(h, 0.0f);
            }
            __syncthreads();
            if (tid < 64) {
                float s = b_up[tid];
                #pragma unroll
                for (int m = 0; m < 4; m++)
                    s = fmaf(hidden[m], __ldg(&w_up[tid * 4 + m]), s);
                __stcg(&g_scale[b * 64 + tid], 1.0f / (1.0f + expf(-s)));
            }
            __syncthreads();
            if (tid == 0) {
                __threadfence();                // release g_scale[b*64..]
                g_ready[b] = 1u;
            }
        }
    } else {
        // ================= SCALE (one 16 KB chunk, ILP-4) ==================
        const unsigned sbid = blockIdx.x - NPLANES;
        const unsigned b    = sbid >> 10;       // 1024 chunks per batch

        if (tid == 0) {
            while (g_ready[b] == 0u) __nanosleep(64);   // read-only spin
            __threadfence();                            // acquire g_scale
        }
        __syncthreads();

        const size_t base = (size_t)sbid * 1024 + tid;
        const float4* __restrict__ px = reinterpret_cast<const float4*>(x);
        float4*       __restrict__ py = reinterpret_cast<float4*>(y);
        const float s = __ldcg(&g_scale[base >> 14]);   // uniform in block

        float4 v0 = __ldcs(px + base);
        float4 v1 = __ldcs(px + base + 256);
        float4 v2 = __ldcs(px + base + 512);
        float4 v3 = __ldcs(px + base + 768);

        v0.x *= s; v0.y *= s; v0.z *= s; v0.w *= s;
        v1.x *= s; v1.y *= s; v1.z *= s; v1.w *= s;
        v2.x *= s; v2.y *= s; v2.z *= s; v2.w *= s;
        v3.x *= s; v3.y *= s; v3.z *= s; v3.w *= s;

        __stcs(py + base,       v0);
        __stcs(py + base + 256, v1);
        __stcs(py + base + 512, v2);
        __stcs(py + base + 768, v3);

        __syncthreads();                        // whole block past the wait
        if (tid == 0) {
            unsigned old = atomicAdd(&g_sdone[b], 1u);
            if (old == SCALE_PB - 1u) {         // last scaler of batch b:
                g_ready[b] = 0u;                // reset flag for next replay
                atomicSub(&g_sdone[b], SCALE_PB);
            }
        }
    }
}

// ---------------------------------------------------------------------------
extern "C" void kernel_launch(void* const* d_in, const int* in_sizes, int n_in,
                              void* d_out, int out_size)
{
    const float* trans_b = (const float*)d_in[0];
    const float* w_down  = (const float*)d_in[1];
    const float* b_down  = (const float*)d_in[2];
    const float* w_up    = (const float*)d_in[3];
    const float* b_up    = (const float*)d_in[4];
    float* out = (float*)d_out;

    se_onelaunch_kernel<<<NPLANES + SCALE_BLKS, 256>>>(
        trans_b, out, w_down, b_down, w_up, b_up);
}